// round 11
// baseline (speedup 1.0000x reference)
#include <cuda_runtime.h>
#include <cstdint>

// CostVolumeBidirectional: f1,f2 (8,96,96,320) f32 -> out (8,9,96,320) f32
// out[b][d][h][w] = (1/96) * sum_c f1[b][c][h][w] * f2[b][c][h][w-(d-4)]
// zero where w-(d-4) outside [0,320).
//
// R11: cp.async 6-deep smem pipeline. R8/R10 plateaued at DRAM=53% because
// register-resident loads cap bytes-in-flight (~64 regs). Now each channel's
// f1/f2 slices stream through smem via cp.async.cg (latency absorbed by
// pipeline depth, zero register cost), windows come from LDS with smem halos
// (zfill for out-of-row), and the reduction buffer is unioned with the pipe
// so blocks stay at 25KB smem -> 8 blocks/SM -> all 960 blocks resident.

#define BS 8
#define FS 96
#define H  96
#define W  320
#define WQ (W / 4)        // 80 float4 groups per row
#define NP 9              // disparity planes

#define GROUPS 64         // float4-groups per block
#define CHUNKS 2          // channel chunks
#define CHP (FS / CHUNKS) // 48 channels per thread
#define BLOCK (GROUPS * CHUNKS)  // 128 threads
#define DEPTH 6           // cp.async pipeline stages (48 % 6 == 0)

struct __align__(16) SmemPipe {
    float4 f2[CHUNKS][DEPTH][GROUPS + 2];  // [halo_l, 64 groups, halo_r]
    float4 f1[CHUNKS][DEPTH][GROUPS];
};
union SmemU {
    SmemPipe pipe;                         // 24,960 B
    float4 red[CHUNKS][GROUPS][NP];        // 18,432 B (epilogue only)
};

__device__ __forceinline__ void cp_async16(uint32_t dst, const void* src, int src_size) {
    asm volatile("cp.async.cg.shared.global [%0], [%1], 16, %2;\n"
                 :: "r"(dst), "l"(src), "r"(src_size));
}
__device__ __forceinline__ void cp_commit() {
    asm volatile("cp.async.commit_group;\n" ::: "memory");
}
__device__ __forceinline__ void cp_wait_5() {
    asm volatile("cp.async.wait_group 5;\n" ::: "memory");
}

__global__ __launch_bounds__(BLOCK, 8)
void cost_volume_kernel(const float* __restrict__ f1,
                        const float* __restrict__ f2,
                        float* __restrict__ out) {
    __shared__ SmemU sm;

    const int tid = threadIdx.x;
    const int g   = tid & (GROUPS - 1);
    const int cc  = tid >> 6;

    const int t  = blockIdx.x * GROUPS + g;   // global float4-group id
    const int wq = t % WQ;
    const int bh = t / WQ;
    const int h  = bh % H;
    const int b  = bh / H;

    const int cs = H * W;
    const size_t base = ((size_t)b * FS + cc * CHP) * cs + (size_t)h * W + (size_t)wq * 4;
    const float* p1 = f1 + base;
    const float* p2 = f2 + base;

    const bool hasL = (wq > 0);
    const bool hasR = (wq < WQ - 1);

    const uint32_t s_f2 = (uint32_t)__cvta_generic_to_shared(&sm.pipe.f2[cc][0][0]);
    const uint32_t s_f1 = (uint32_t)__cvta_generic_to_shared(&sm.pipe.f1[cc][0][0]);
    const uint32_t f2_stage = (GROUPS + 2) * 16;
    const uint32_t f1_stage = GROUPS * 16;

    // Issue one channel's slices into pipeline slot.
    // Halo neighbors at +/-1 group are contiguous in memory within a row;
    // out-of-row halos are zfilled (src_size=0) with a clamped (valid) address.
    auto issue = [&](int ch, int slot) {
        const float* q1 = p1 + (size_t)ch * cs;
        const float* q2 = p2 + (size_t)ch * cs;
        cp_async16(s_f1 + slot * f1_stage + g * 16, q1, 16);
        cp_async16(s_f2 + slot * f2_stage + (g + 1) * 16, q2, 16);
        if (g == 0)
            cp_async16(s_f2 + slot * f2_stage, hasL ? (q2 - 4) : q2, hasL ? 16 : 0);
        if (g == GROUPS - 1)
            cp_async16(s_f2 + slot * f2_stage + (GROUPS + 1) * 16,
                       hasR ? (q2 + 4) : q2, hasR ? 16 : 0);
    };

    // prologue: fill the pipeline
#pragma unroll
    for (int s0 = 0; s0 < DEPTH; s0++) {
        issue(s0, s0);
        cp_commit();
    }

    float acc[NP][4];
#pragma unroll
    for (int d = 0; d < NP; d++)
#pragma unroll
        for (int k = 0; k < 4; k++) acc[d][k] = 0.0f;

    const float4 z4 = make_float4(0.f, 0.f, 0.f, 0.f);

#pragma unroll 6
    for (int c = 0; c < CHP; c++) {
        const int slot = c % DEPTH;

        cp_wait_5();          // own oldest stage complete (<=5 pending)
        __syncthreads();      // publish all threads' stage data

        const float4* f2s = &sm.pipe.f2[cc][slot][0];
        float4 a = sm.pipe.f1[cc][slot][g];
        float4 m = f2s[g + 1];
        float4 l = hasL ? f2s[g] : z4;
        float4 r = hasR ? f2s[g + 2] : z4;

        float w12[12] = {l.x, l.y, l.z, l.w,
                         m.x, m.y, m.z, m.w,
                         r.x, r.y, r.z, r.w};
        float av[4] = {a.x, a.y, a.z, a.w};

        // plane d => shift i = d-4; f2 window index = k + 8 - d
#pragma unroll
        for (int d = 0; d < NP; d++) {
#pragma unroll
            for (int k = 0; k < 4; k++) {
                acc[d][k] = fmaf(av[k], w12[k + 8 - d], acc[d][k]);
            }
        }

        __syncthreads();      // all reads of this slot done before reissue
        if (c + DEPTH < CHP) issue(c + DEPTH, slot);
        cp_commit();          // exactly one group per iter keeps wait_group aligned
    }

    // epilogue: partials -> smem (red aliases pipe; all pipe reads completed
    // at the final in-loop barrier), then 2-way reduce + store.
    __syncthreads();
#pragma unroll
    for (int d = 0; d < NP; d++) {
        sm.red[cc][g][d] = make_float4(acc[d][0], acc[d][1], acc[d][2], acc[d][3]);
    }
    __syncthreads();

    const float inv = 1.0f / (float)FS;
    for (int item = tid; item < GROUPS * NP; item += BLOCK) {
        const int g2 = item / NP;
        const int d  = item % NP;

        float4 a0 = sm.red[0][g2][d];
        float4 a1 = sm.red[1][g2][d];

        float4 o;
        o.x = (a0.x + a1.x) * inv;
        o.y = (a0.y + a1.y) * inv;
        o.z = (a0.z + a1.z) * inv;
        o.w = (a0.w + a1.w) * inv;

        const int t2  = blockIdx.x * GROUPS + g2;
        const int wq2 = t2 % WQ;
        const int bh2 = t2 / WQ;
        const int h2  = bh2 % H;
        const int b2  = bh2 / H;

        const size_t oidx = (((size_t)b2 * NP + d) * H + h2) * W + (size_t)wq2 * 4;
        *(float4*)(out + oidx) = o;
    }
}

extern "C" void kernel_launch(void* const* d_in, const int* in_sizes, int n_in,
                              void* d_out, int out_size) {
    const float* f1 = (const float*)d_in[0];
    const float* f2 = (const float*)d_in[1];
    float* out = (float*)d_out;

    const int total_groups = BS * H * WQ;          // 61440
    const int grid = total_groups / GROUPS;        // 960 blocks
    cost_volume_kernel<<<grid, BLOCK>>>(f1, f2, out);
}

// round 12
// speedup vs baseline: 1.1032x; 1.1032x over previous
#include <cuda_runtime.h>

// CostVolumeBidirectional: f1,f2 (8,96,96,320) f32 -> out (8,9,96,320) f32
// out[b][d][h][w] = (1/96) * sum_c f1[b][c][h][w] * f2[b][c][h][w-(d-4)]
// zero where w-(d-4) outside [0,320).
//
// R12: R10 structure (4-col tile, CHUNKS=2, 128-thr blocks, register loads)
// but the f2 halo (l/r float4s) comes from warp shuffles of the neighbor
// lane's m instead of redundant LDGs. Cuts L1tex wavefronts per warp-channel
// ~16-20 -> ~10 (L1tex was co-limiting with DRAM at 53%). Only lanes 0/31
// issue predicated 1-lane edge loads; row-boundary cases stay masked by
// hasL/hasR exactly as before.

#define BS 8
#define FS 96
#define H  96
#define W  320
#define WQ (W / 4)      // 80 float4 groups per row
#define NP 9            // disparity planes

#define GROUPS 64       // float4-groups per block
#define CHUNKS 2        // channel chunks per group
#define CHP (FS / CHUNKS)  // 48 channels per thread
#define BLOCK (GROUPS * CHUNKS)   // 128 threads

__global__ __launch_bounds__(BLOCK, 8)
void cost_volume_kernel(const float* __restrict__ f1,
                        const float* __restrict__ f2,
                        float* __restrict__ out) {
    // partial accumulators: [chunk][group][plane] as float4 (4 columns)
    __shared__ float4 s[CHUNKS][GROUPS][NP];   // 18 KB

    const int tid  = threadIdx.x;
    const int g    = tid & (GROUPS - 1);
    const int cc   = tid >> 6;
    const int lane = tid & 31;

    const int t  = blockIdx.x * GROUPS + g;    // global float4-group id
    const int wq = t % WQ;
    const int bh = t / WQ;
    const int h  = bh % H;
    const int b  = bh / H;

    float acc[NP][4];
#pragma unroll
    for (int d = 0; d < NP; d++)
#pragma unroll
        for (int k = 0; k < 4; k++) acc[d][k] = 0.0f;

    const int cs = H * W;
    const size_t base = ((size_t)b * FS + cc * CHP) * cs + (size_t)h * W + (size_t)wq * 4;
    const float* p1 = f1 + base;
    const float* p2 = f2 + base;

    const bool hasL = (wq > 0);
    const bool hasR = (wq < WQ - 1);
    // lanes that must fetch their halo from memory (warp edge, within row)
    const bool edgeL = (lane == 0)  && hasL;
    const bool edgeR = (lane == 31) && hasR;
    const float4 z4 = make_float4(0.f, 0.f, 0.f, 0.f);

#pragma unroll 4
    for (int c = 0; c < CHP; c++) {
        const float* q1 = p1 + (size_t)c * cs;
        const float* q2 = p2 + (size_t)c * cs;

        float4 a = *(const float4*)(q1);
        float4 m = *(const float4*)(q2);

        // halo via shuffle of neighbor lane's m (lane-1 holds group t-1, which
        // is wq-1 of the same row whenever hasL; garbage otherwise but masked)
        float4 l, r;
        l.x = __shfl_up_sync(0xffffffffu, m.x, 1);
        l.y = __shfl_up_sync(0xffffffffu, m.y, 1);
        l.z = __shfl_up_sync(0xffffffffu, m.z, 1);
        l.w = __shfl_up_sync(0xffffffffu, m.w, 1);
        r.x = __shfl_down_sync(0xffffffffu, m.x, 1);
        r.y = __shfl_down_sync(0xffffffffu, m.y, 1);
        r.z = __shfl_down_sync(0xffffffffu, m.z, 1);
        r.w = __shfl_down_sync(0xffffffffu, m.w, 1);

        if (edgeL) l = *(const float4*)(q2 - 4);   // 1-lane predicated LDG
        if (edgeR) r = *(const float4*)(q2 + 4);   // 1-lane predicated LDG
        if (!hasL) l = z4;
        if (!hasR) r = z4;

        float w12[12] = {l.x, l.y, l.z, l.w,
                         m.x, m.y, m.z, m.w,
                         r.x, r.y, r.z, r.w};
        float av[4] = {a.x, a.y, a.z, a.w};

        // plane d => shift i = d-4; f2 window index = k + 8 - d
#pragma unroll
        for (int d = 0; d < NP; d++) {
#pragma unroll
            for (int k = 0; k < 4; k++) {
                acc[d][k] = fmaf(av[k], w12[k + 8 - d], acc[d][k]);
            }
        }
    }

    // stash partials
#pragma unroll
    for (int d = 0; d < NP; d++) {
        s[cc][g][d] = make_float4(acc[d][0], acc[d][1], acc[d][2], acc[d][3]);
    }
    __syncthreads();

    // reduce 2 chunks + write out: 64 groups x 9 planes = 576 float4 stores
    const float inv = 1.0f / (float)FS;
    for (int item = tid; item < GROUPS * NP; item += BLOCK) {
        const int g2 = item / NP;
        const int d  = item % NP;

        float4 a0 = s[0][g2][d];
        float4 a1 = s[1][g2][d];

        float4 o;
        o.x = (a0.x + a1.x) * inv;
        o.y = (a0.y + a1.y) * inv;
        o.z = (a0.z + a1.z) * inv;
        o.w = (a0.w + a1.w) * inv;

        const int t2  = blockIdx.x * GROUPS + g2;
        const int wq2 = t2 % WQ;
        const int bh2 = t2 / WQ;
        const int h2  = bh2 % H;
        const int b2  = bh2 / H;

        const size_t oidx = (((size_t)b2 * NP + d) * H + h2) * W + (size_t)wq2 * 4;
        *(float4*)(out + oidx) = o;
    }
}

extern "C" void kernel_launch(void* const* d_in, const int* in_sizes, int n_in,
                              void* d_out, int out_size) {
    const float* f1 = (const float*)d_in[0];
    const float* f2 = (const float*)d_in[1];
    float* out = (float*)d_out;

    const int total_groups = BS * H * WQ;          // 61440
    const int grid = total_groups / GROUPS;        // 960 blocks
    cost_volume_kernel<<<grid, BLOCK>>>(f1, f2, out);
}